// round 13
// baseline (speedup 1.0000x reference)
#include <cuda_runtime.h>
#include <cstdint>
#include <cstddef>

// Problem constants
#define B_ 64
#define T_ 1024
#define I_ 128
#define H_ 256

#define GRP 8              // batch groups (8 batches each)
#define BG 8
#define CPG 16             // CTAs per group (fused L1+L2), 16 cols of each layer
#define NCTA 128
#define TPB 256

#define OUT_Y2 ((size_t)B_ * T_ * H_)

// -------- device scratch --------
// Fused state slab S[t] = [ h1(t) : 8b x 256k | h2(t-1) : 8b x 256k ] = 16KB
__device__ __align__(16) float g_xpre[(size_t)B_ * T_ * 512];             // [b][t][512]
__device__ __align__(16) float g_st[(size_t)(T_ + 2) * GRP * 4096];       // [t][g][4096]
__device__ unsigned g_cnt[GRP][T_ + 2];

// -------- PTX helpers --------
typedef unsigned long long u64;
__device__ __forceinline__ uint32_t s2u(const void* p) {
    return (uint32_t)__cvta_generic_to_shared(p);
}
__device__ __forceinline__ void mbar_init(uint32_t a, uint32_t cnt) {
    asm volatile("mbarrier.init.shared.b64 [%0], %1;" :: "r"(a), "r"(cnt) : "memory");
}
__device__ __forceinline__ void mbar_expect(uint32_t a, uint32_t bytes) {
    asm volatile("mbarrier.arrive.expect_tx.shared.b64 _, [%0], %1;" :: "r"(a), "r"(bytes) : "memory");
}
__device__ __forceinline__ void bulk_g2s(uint32_t dst, const void* src, uint32_t bytes, uint32_t mbar) {
    asm volatile("cp.async.bulk.shared::cluster.global.mbarrier::complete_tx::bytes [%0], [%1], %2, [%3];"
                 :: "r"(dst), "l"(src), "r"(bytes), "r"(mbar) : "memory");
}
__device__ __forceinline__ void mbar_wait(uint32_t a, uint32_t parity) {
    asm volatile("{\n\t"
                 ".reg .pred P;\n\t"
                 "W%=:\n\t"
                 "mbarrier.try_wait.parity.acquire.cta.shared::cta.b64 P, [%0], %1, 0x989680;\n\t"
                 "@P bra D%=;\n\t"
                 "bra W%=;\n\t"
                 "D%=:\n\t"
                 "}" :: "r"(a), "r"(parity) : "memory");
}
__device__ __forceinline__ void fence_async() {
    asm volatile("fence.proxy.async.shared::cta;" ::: "memory");
}
__device__ __forceinline__ unsigned ld_acq(const unsigned* p) {
    unsigned v;
    asm volatile("ld.global.acquire.gpu.u32 %0, [%1];" : "=r"(v) : "l"(p) : "memory");
    return v;
}
__device__ __forceinline__ void red_add1(unsigned* p) {
    asm volatile("red.release.gpu.global.add.u32 [%0], %1;" :: "l"(p), "r"(1u) : "memory");
}
__device__ __forceinline__ u64 pack2(float x, float y) {
    u64 r; asm("mov.b64 %0, {%1, %2};" : "=l"(r) : "f"(x), "f"(y)); return r;
}
__device__ __forceinline__ void unpack2(u64 v, float& x, float& y) {
    asm("mov.b64 {%0, %1}, %2;" : "=f"(x), "=f"(y) : "l"(v));
}
__device__ __forceinline__ u64 fma2(u64 a, u64 b, u64 c) {
    u64 d; asm("fma.rn.f32x2 %0, %1, %2, %3;" : "=l"(d) : "l"(a), "l"(b), "l"(c)); return d;
}
__device__ __forceinline__ u64 add2(u64 a, u64 b) {
    u64 d; asm("add.rn.f32x2 %0, %1, %2;" : "=l"(d) : "l"(a), "l"(b)); return d;
}
__device__ __forceinline__ float sigm(float x) { return 1.f / (1.f + __expf(-x)); }
__device__ __forceinline__ float tanh_f(float x) { return 1.f - 2.f / (1.f + __expf(2.f * x)); }

// ============================================================
// Phase 1: x-projection GEMM (unchanged)
// ============================================================
__global__ void __launch_bounds__(256) xproj_kernel(
    const float* __restrict__ x,
    const float* __restrict__ Wf1, const float* __restrict__ bf1,
    const float* __restrict__ Wc1, const float* __restrict__ bc1)
{
    __shared__ float As[64][68];
    __shared__ float Bs[64][68];
    const int bm = blockIdx.x;
    const int bn = blockIdx.y;
    const int tid = threadIdx.x;
    const int tx = tid & 15, ty = tid >> 4;

    const float* W; const float* bias; int jb;
    if (bn < 4) { W = Wf1; bias = bf1; jb = bn * 64; }
    else        { W = Wc1; bias = bc1; jb = (bn - 4) * 64; }

    float acc[4][4];
#pragma unroll
    for (int i = 0; i < 4; ++i)
#pragma unroll
        for (int j = 0; j < 4; ++j) acc[i][j] = 0.f;

    for (int k0 = 0; k0 < 128; k0 += 64) {
#pragma unroll
        for (int i = 0; i < 4; ++i) {
            int idx = tid + i * 256;
            int r = idx >> 4, kv = idx & 15;
            float4 v = *(const float4*)(x + (size_t)(bm * 64 + r) * 128 + k0 + kv * 4);
            *(float4*)&As[r][kv * 4] = v;
        }
#pragma unroll
        for (int i = 0; i < 4; ++i) {
            int idx = tid + i * 256;
            int kk = idx >> 4, cv = idx & 15;
            float4 v = *(const float4*)(W + (size_t)(k0 + kk) * 256 + jb + cv * 4);
            *(float4*)&Bs[kk][cv * 4] = v;
        }
        __syncthreads();
#pragma unroll 16
        for (int kk = 0; kk < 64; ++kk) {
            float a0 = As[ty * 4 + 0][kk];
            float a1 = As[ty * 4 + 1][kk];
            float a2 = As[ty * 4 + 2][kk];
            float a3 = As[ty * 4 + 3][kk];
            float4 bv = *(const float4*)&Bs[kk][tx * 4];
            acc[0][0] = fmaf(a0, bv.x, acc[0][0]);
            acc[0][1] = fmaf(a0, bv.y, acc[0][1]);
            acc[0][2] = fmaf(a0, bv.z, acc[0][2]);
            acc[0][3] = fmaf(a0, bv.w, acc[0][3]);
            acc[1][0] = fmaf(a1, bv.x, acc[1][0]);
            acc[1][1] = fmaf(a1, bv.y, acc[1][1]);
            acc[1][2] = fmaf(a1, bv.z, acc[1][2]);
            acc[1][3] = fmaf(a1, bv.w, acc[1][3]);
            acc[2][0] = fmaf(a2, bv.x, acc[2][0]);
            acc[2][1] = fmaf(a2, bv.y, acc[2][1]);
            acc[2][2] = fmaf(a2, bv.z, acc[2][2]);
            acc[2][3] = fmaf(a2, bv.w, acc[2][3]);
            acc[3][0] = fmaf(a3, bv.x, acc[3][0]);
            acc[3][1] = fmaf(a3, bv.y, acc[3][1]);
            acc[3][2] = fmaf(a3, bv.z, acc[3][2]);
            acc[3][3] = fmaf(a3, bv.w, acc[3][3]);
        }
        __syncthreads();
    }
#pragma unroll
    for (int i = 0; i < 4; ++i) {
        int r = bm * 64 + ty * 4 + i;
        float4 o;
        o.x = acc[i][0] + bias[jb + tx * 4 + 0];
        o.y = acc[i][1] + bias[jb + tx * 4 + 1];
        o.z = acc[i][2] + bias[jb + tx * 4 + 2];
        o.w = acc[i][3] + bias[jb + tx * 4 + 3];
        *(float4*)&g_xpre[(size_t)r * 512 + bn * 64 + tx * 4] = o;
    }
}

// ============================================================
__global__ void init_kernel()
{
    int i = blockIdx.x * blockDim.x + threadIdx.x;      // 32768 threads
    if (i < GRP * 4096) g_st[i] = 0.f;                  // S[0] = [h1(0)=0 | h2(-1)=0]
    if (i < GRP * (T_ + 2)) ((unsigned*)g_cnt)[i] = 0;
}

// ============================================================
// Phase 2: fused-layer persistent recurrence
//   SMEM: [0,16384) buf = S[t] pull dest (h1 | h2 halves)
//         [16384,49152) red u64[2 phase][8 warp][8 b][2 gate][16 col]
//         [49152,+16)   mbars mb0 (h1 half), mb1 (h2 half)
// ============================================================
#define SM_BUF  0
#define SM_RED  16384
#define SM_MBAR 49152
#define SMEM_BYTES 49184

extern __shared__ __align__(16) char smem[];

__global__ void __launch_bounds__(TPB, 1)
recur_kernel(const float* __restrict__ Wf1, const float* __restrict__ Wc1,
             const float* __restrict__ Wf2, const float* __restrict__ bf2,
             const float* __restrict__ Wc2, const float* __restrict__ bc2,
             float* __restrict__ out)
{
    const int tid = threadIdx.x;
    const int warp = tid >> 5, lane = tid & 31;
    const int cid = blockIdx.x;
    const int g = cid >> 4;
    const int c = cid & 15;
    const int j0 = c * 16;
    const int col = lane & 15;
    const int kh = lane >> 4;
    const int jg = j0 + col;

    float* buf = (float*)(smem + SM_BUF);
    u64*   red = (u64*)(smem + SM_RED);
    const uint32_t mb0 = s2u(smem + SM_MBAR);
    const uint32_t mb1 = mb0 + 8;

    // Register-resident weights (k-pair packed)
    u64 w1f[8], w1c[8];            // L1: 16 k per lane
#pragma unroll
    for (int p = 0; p < 8; ++p) {
        int k = warp * 32 + kh * 16 + 2 * p;
        w1f[p] = pack2(Wf1[(size_t)(I_ + k) * H_ + jg], Wf1[(size_t)(I_ + k + 1) * H_ + jg]);
        w1c[p] = pack2(Wc1[(size_t)(I_ + k) * H_ + jg], Wc1[(size_t)(I_ + k + 1) * H_ + jg]);
    }
    u64 w2f[16], w2c[16];          // L2: 32 k per lane, k = warp*64 + kh*32 + 2p
#pragma unroll
    for (int p = 0; p < 16; ++p) {
        int k = warp * 64 + kh * 32 + 2 * p;
        w2f[p] = pack2(Wf2[(size_t)k * H_ + jg], Wf2[(size_t)(k + 1) * H_ + jg]);
        w2c[p] = pack2(Wc2[(size_t)k * H_ + jg], Wc2[(size_t)(k + 1) * H_ + jg]);
    }
    // L2 input = concat(y1, h2): warps 0-3 read h1/y1 half, warps 4-7 read h2 half
    const int  l2half = (warp >> 2);                      // 0: y1 half, 1: h2 half
    const int  l2off  = (warp & 3) * 32 + kh * 16;        // u64 units within batch row

    if (tid == 0) { mbar_init(mb0, 1); mbar_init(mb1, 1); }
    __syncthreads();

    // Gate-thread identity: tid -> (layer, batch, col)
    const int gl = tid >> 7;           // 0 = L1 outputs, 1 = L2 outputs
    const int gb = (tid >> 4) & 7;
    const int gc = tid & 15;
    const int gj = j0 + gc;
    float xf = 0.f, xc = 0.f, b2f = 0.f, b2c = 0.f;
    const float* xbase = g_xpre + ((size_t)(g * BG + gb) * T_) * 512;
    if (gl == 0) {
        xf = __ldcg(xbase + gj);
        xc = __ldcg(xbase + 256 + gj);
    } else {
        b2f = __ldg(bf2 + gj);
        b2c = __ldg(bc2 + gj);
    }

    unsigned* cnt = g_cnt[g];
    unsigned ph = 0;

    for (int t = 0; t <= T_; ++t) {
        if (tid == 0) {
            if (t > 0) { while (ld_acq(&cnt[t - 1]) < CPG) {} }
            fence_async();
            const float* src = g_st + ((size_t)t * GRP + g) * 4096;
            mbar_expect(mb0, 8192);
            bulk_g2s(s2u(buf), src, 8192, mb0);
            mbar_expect(mb1, 8192);
            bulk_g2s(s2u(buf) + 8192, src + 2048, 8192, mb1);
        }

        u64 af[8], ac[8];
        // ---------------- Phase L1 (h1 @ t -> h1 @ t+1) ----------------
        mbar_wait(mb0, ph);
        if (t < T_) {
#pragma unroll
            for (int b = 0; b < 8; ++b) { af[b] = 0; ac[b] = 0; }
#pragma unroll
            for (int b = 0; b < 8; ++b) {
                const u64* hp = (const u64*)(buf + b * 256) + (warp * 16 + kh * 8);
#pragma unroll
                for (int i = 0; i < 4; ++i) {
                    ulonglong2 h2 = *(const ulonglong2*)(hp + 2 * i);
                    af[b] = fma2(h2.x, w1f[2 * i], af[b]);
                    af[b] = fma2(h2.y, w1f[2 * i + 1], af[b]);
                    ac[b] = fma2(h2.x, w1c[2 * i], ac[b]);
                    ac[b] = fma2(h2.y, w1c[2 * i + 1], ac[b]);
                }
            }
#pragma unroll
            for (int b = 0; b < 8; ++b) {
                af[b] = add2(af[b], __shfl_xor_sync(0xffffffffu, af[b], 16));
                ac[b] = add2(ac[b], __shfl_xor_sync(0xffffffffu, ac[b], 16));
            }
            if (kh == 0) {
#pragma unroll
                for (int b = 0; b < 8; ++b) {
                    red[((0 * 8 + warp) * 16 + b * 2 + 0) * 16 + col] = af[b];
                    red[((0 * 8 + warp) * 16 + b * 2 + 1) * 16 + col] = ac[b];
                }
            }
        }
        // ---------------- Phase L2 (y1(t-1)=h1(t), h2(t-1) -> h2(t)) ----------------
        mbar_wait(mb1, ph);
        if (t > 0) {
            const float* l2base = buf + l2half * 2048;
#pragma unroll
            for (int b = 0; b < 8; ++b) { af[b] = 0; ac[b] = 0; }
#pragma unroll
            for (int b = 0; b < 8; ++b) {
                const u64* hp = (const u64*)(l2base + b * 256) + l2off;
#pragma unroll
                for (int i = 0; i < 8; ++i) {
                    ulonglong2 h2 = *(const ulonglong2*)(hp + 2 * i);
                    af[b] = fma2(h2.x, w2f[2 * i], af[b]);
                    af[b] = fma2(h2.y, w2f[2 * i + 1], af[b]);
                    ac[b] = fma2(h2.x, w2c[2 * i], ac[b]);
                    ac[b] = fma2(h2.y, w2c[2 * i + 1], ac[b]);
                }
            }
#pragma unroll
            for (int b = 0; b < 8; ++b) {
                af[b] = add2(af[b], __shfl_xor_sync(0xffffffffu, af[b], 16));
                ac[b] = add2(ac[b], __shfl_xor_sync(0xffffffffu, ac[b], 16));
            }
            if (kh == 0) {
#pragma unroll
                for (int b = 0; b < 8; ++b) {
                    red[((1 * 8 + warp) * 16 + b * 2 + 0) * 16 + col] = af[b];
                    red[((1 * 8 + warp) * 16 + b * 2 + 1) * 16 + col] = ac[b];
                }
            }
        }
        __syncthreads();

        // ---------------- Gates: 256 threads, one output each ----------------
        float* dslab = g_st + ((size_t)(t + 1) * GRP + g) * 4096;
        if (gl == 0) {
            if (t < T_) {
                u64 sf = red[((0 * 8 + 0) * 16 + gb * 2 + 0) * 16 + gc];
                u64 sc = red[((0 * 8 + 0) * 16 + gb * 2 + 1) * 16 + gc];
#pragma unroll
                for (int w = 1; w < 8; ++w) {
                    sf = add2(sf, red[((0 * 8 + w) * 16 + gb * 2 + 0) * 16 + gc]);
                    sc = add2(sc, red[((0 * 8 + w) * 16 + gb * 2 + 1) * 16 + gc]);
                }
                float e, o;
                unpack2(sf, e, o); float pf = e + o + xf;
                unpack2(sc, e, o); float pc = e + o + xc;
                float f = sigm(pf);
                float cg = tanh_f(pc);
                float hold = buf[gb * 256 + gj];
                float hn = fmaf(f, hold - cg, cg);
                dslab[gb * 256 + gj] = hn;
                if (t + 1 < T_) {
                    xf = __ldcg(xbase + (size_t)(t + 1) * 512 + gj);
                    xc = __ldcg(xbase + (size_t)(t + 1) * 512 + 256 + gj);
                }
                if (t == T_ - 1) out[OUT_Y2 + (size_t)(g * BG + gb) * H_ + gj] = hn;
            }
        } else {
            float hn = 0.f;
            if (t > 0) {
                u64 sf = red[((1 * 8 + 0) * 16 + gb * 2 + 0) * 16 + gc];
                u64 sc = red[((1 * 8 + 0) * 16 + gb * 2 + 1) * 16 + gc];
#pragma unroll
                for (int w = 1; w < 8; ++w) {
                    sf = add2(sf, red[((1 * 8 + w) * 16 + gb * 2 + 0) * 16 + gc]);
                    sc = add2(sc, red[((1 * 8 + w) * 16 + gb * 2 + 1) * 16 + gc]);
                }
                float e, o;
                unpack2(sf, e, o); float pf = e + o + b2f;
                unpack2(sc, e, o); float pc = e + o + b2c;
                float f = sigm(pf);
                float cg = tanh_f(pc);
                float hold = buf[2048 + gb * 256 + gj];
                hn = fmaf(f, hold - cg, cg);
                out[((size_t)(g * BG + gb) * T_ + (t - 1)) * H_ + gj] = hn;
                if (t == T_) out[OUT_Y2 + (size_t)B_ * H_ + (size_t)(g * BG + gb) * H_ + gj] = hn;
            }
            dslab[2048 + gb * 256 + gj] = hn;
        }
        __syncthreads();
        if (tid == 0) red_add1(&cnt[t]);
        ph ^= 1;
    }
}

// ============================================================
extern "C" void kernel_launch(void* const* d_in, const int* in_sizes, int n_in,
                              void* d_out, int out_size)
{
    const float* x   = (const float*)d_in[0];
    const float* Wf1 = (const float*)d_in[1];
    const float* bf1 = (const float*)d_in[2];
    const float* Wc1 = (const float*)d_in[3];
    const float* bc1 = (const float*)d_in[4];
    const float* Wf2 = (const float*)d_in[5];
    const float* bf2 = (const float*)d_in[6];
    const float* Wc2 = (const float*)d_in[7];
    const float* bc2 = (const float*)d_in[8];
    float* out = (float*)d_out;

    cudaFuncSetAttribute((const void*)recur_kernel,
                         cudaFuncAttributeMaxDynamicSharedMemorySize, SMEM_BYTES);

    init_kernel<<<128, 256>>>();
    xproj_kernel<<<dim3(1024, 8), 256>>>(x, Wf1, bf1, Wc1, bc1);
    recur_kernel<<<NCTA, TPB, SMEM_BYTES>>>(Wf1, Wc1, Wf2, bf2, Wc2, bc2, out);
}